// round 17
// baseline (speedup 1.0000x reference)
#include <cuda_runtime.h>
#include <cuda_fp16.h>
#include <math.h>
#include <stdint.h>

// Problem constants (fixed shapes for this problem)
#define NN   8192      // nodes (= output classes)
#define FIN  512       // input features
#define HD   64        // hidden dim
#define MAXE (NN * 64) // edges
#define NCB  64        // number of 128-wide column blocks in the big GEMM

// ---------------- device scratch (static allocation; no cudaMalloc) ----------------
__device__ int   g_is64;             // edge_index dtype flag (1 = int64, 0 = int32)
__device__ int   g_hist[NN];         // in-degree histogram (dst counts)
__device__ volatile int g_bsum[32];  // scan: per-block sums (published)
__device__ volatile int g_bflag[32]; // scan: publish flags (re-zeroed each call)
__device__ int   g_row_ptr[NN + 1];  // CSR row pointers (by dst)
__device__ int   g_cursor[NN];       // scatter cursors (preloaded with row starts)
__device__ int   g_col[MAXE];        // CSR column (src) indices
__device__ float g_dinv[NN];         // deg^{-1/2} (deg includes self loop)

// fp16 feature arrays (half the gather traffic in the aggregations)
__device__ __half g_xw16[NN * HD];   // x @ W1, fp16 [NN][HD]
__device__ __half g_h16[NN * HD];    // layer-1 output (post relu), fp16
__device__ __half g_m16[NN * HD];    // M = Â h in fp16 (written by agg2)
__device__ __half g_w216[HD * NN];   // W2 in fp16, row-major [HD][NN]
__device__ __half g_w116[FIN * HD];  // W1 in fp16, row-major [FIN][HD]

// per-(colblock,row) online softmax stats + final log-normalizer
__device__ float g_pmax[NCB * NN];
__device__ float g_psum[NCB * NN];
__device__ float g_lz[NN];

// ---------------- helpers ----------------
__device__ __forceinline__ void ldsm4(uint32_t* r, uint32_t addr) {
    asm volatile("ldmatrix.sync.aligned.m8n8.x4.shared.b16 {%0,%1,%2,%3}, [%4];"
                 : "=r"(r[0]), "=r"(r[1]), "=r"(r[2]), "=r"(r[3]) : "r"(addr));
}
__device__ __forceinline__ void ldsm4t(uint32_t* r, uint32_t addr) {
    asm volatile("ldmatrix.sync.aligned.m8n8.x4.trans.shared.b16 {%0,%1,%2,%3}, [%4];"
                 : "=r"(r[0]), "=r"(r[1]), "=r"(r[2]), "=r"(r[3]) : "r"(addr));
}
__device__ __forceinline__ void mma16816(float* c, const uint32_t* a, const uint32_t* b) {
    asm volatile("mma.sync.aligned.m16n8k16.row.col.f32.f16.f16.f32 "
                 "{%0,%1,%2,%3}, {%4,%5,%6,%7}, {%8,%9}, {%0,%1,%2,%3};"
                 : "+f"(c[0]), "+f"(c[1]), "+f"(c[2]), "+f"(c[3])
                 : "r"(a[0]), "r"(a[1]), "r"(a[2]), "r"(a[3]), "r"(b[0]), "r"(b[1]));
}

// ---------------- kernel W: convert W1, W2 to fp16 + zero hist/flags --------
__global__ void k_convert_w(const float* __restrict__ W1, const float* __restrict__ W2) {
    int i = blockIdx.x * blockDim.x + threadIdx.x;
    if (i < NN) g_hist[i] = 0;
    if (i < 32) g_bflag[i] = 0;
    if (i < NN * HD / 4) {
        float4 w4 = *(const float4*)&W2[4 * i];
        __half2* wo = (__half2*)g_w216;
        wo[2 * i]     = __floats2half2_rn(w4.x, w4.y);
        wo[2 * i + 1] = __floats2half2_rn(w4.z, w4.w);
    } else {
        int j = i - NN * HD / 4;   // [0, FIN*HD/4)
        float4 w4 = *(const float4*)&W1[4 * j];
        __half2* wo = (__half2*)g_w116;
        wo[2 * j]     = __floats2half2_rn(w4.x, w4.y);
        wo[2 * j + 1] = __floats2half2_rn(w4.z, w4.w);
    }
}

// ---------------- kernel 1: histogram of dst (4 edges/thread, MLP=4) --------
__global__ void k_hist(const void* ei, const int* eiw, int E) {
    __shared__ int s_cnt;
    int t = threadIdx.x;
    if (t == 0) s_cnt = 0;
    __syncthreads();
    if (t < 256) {
        // inspect odd 32-bit words: all ~0 => int64 (ids < 8192), random => int32
        unsigned zero = __ballot_sync(0xffffffffu, eiw[2 * t + 1] == 0);
        if ((t & 31) == 0) atomicAdd(&s_cnt, __popc(zero));
    }
    __syncthreads();
    int is64 = s_cnt > 200;
    if (blockIdx.x == 0 && t == 0) g_is64 = is64;   // for k_scatter
    int base = blockIdx.x * 1024 + t;
    int d[4];
#pragma unroll
    for (int j = 0; j < 4; j++) {
        int e = base + j * 256;
        d[j] = -1;
        if (e < E)
            d[j] = is64 ? (int)((const long long*)ei)[(long long)E + e]
                        : ((const int*)ei)[E + e];
    }
#pragma unroll
    for (int j = 0; j < 4; j++)
        if (d[j] >= 0) atomicAdd(&g_hist[d[j]], 1);
}

// ---------------- kernel 2: single-pass scan (32 blocks, chained publish) ---
// exclusive scan of g_hist into g_row_ptr/g_cursor, plus dinv.
__global__ void k_scan() {
    int t = threadIdx.x, lane = t & 31, wid = t >> 5, b = blockIdx.x;
    int idx = b * 256 + t;
    int v = g_hist[idx];

    // intra-block exclusive prefix
    int incl = v;
#pragma unroll
    for (int off = 1; off < 32; off <<= 1) {
        int u = __shfl_up_sync(0xffffffffu, incl, off);
        if (lane >= off) incl += u;
    }
    __shared__ int ws[8];
    __shared__ int s_tot, s_off;
    if (lane == 31) ws[wid] = incl;
    __syncthreads();
    if (wid == 0 && lane < 8) {
        int wv = ws[lane];
        int wi = wv;
#pragma unroll
        for (int off = 1; off < 8; off <<= 1) {
            int u = __shfl_up_sync(0xffu, wi, off);
            if (lane >= off) wi += u;
        }
        ws[lane] = wi - wv;
        if (lane == 7) s_tot = wi;
    }
    __syncthreads();
    int excl_in_block = ws[wid] + incl - v;

    // publish block total, then sum all previous blocks' totals
    if (t == 0) {
        g_bsum[b] = s_tot;
        __threadfence();
        g_bflag[b] = 1;
    }
    if (wid == 0) {
        int pv = 0;
        if (lane < b) {
            while (g_bflag[lane] == 0) {}
            pv = g_bsum[lane];
        }
#pragma unroll
        for (int off = 16; off > 0; off >>= 1)
            pv += __shfl_xor_sync(0xffffffffu, pv, off);
        if (lane == 0) s_off = pv;
    }
    __syncthreads();

    int excl = s_off + excl_in_block;
    g_row_ptr[idx] = excl;
    g_cursor[idx]  = excl;
    g_dinv[idx] = rsqrtf((float)v + 1.0f);
    if (b == 31 && t == 255) g_row_ptr[NN] = excl + v;
}

// ---------------- kernel 3: scatter src into CSR (4 edges/thread) -----------
__global__ void k_scatter(const void* ei, int E) {
    int base = blockIdx.x * 1024 + threadIdx.x;
    int is64 = g_is64;
    int s[4], d[4];
#pragma unroll
    for (int j = 0; j < 4; j++) {
        int e = base + j * 256;
        d[j] = -1;
        if (e < E) {
            if (is64) {
                s[j] = (int)((const long long*)ei)[e];
                d[j] = (int)((const long long*)ei)[(long long)E + e];
            } else {
                s[j] = ((const int*)ei)[e];
                d[j] = ((const int*)ei)[E + e];
            }
        }
    }
#pragma unroll
    for (int j = 0; j < 4; j++) {
        if (d[j] >= 0) {
            int pos = atomicAdd(&g_cursor[d[j]], 1);
            g_col[pos] = s[j];
        }
    }
}

// ---------------- kernel 4: XW = x(8192x512) @ W1(512x64) via fp16 MMA ------
// 128-row tile per CTA (grid 64), 8 warps as 4x2 (32 rows x 32 cols each).
__global__ __launch_bounds__(256) void k_xw(const float* __restrict__ x) {
    __shared__ __align__(16) __half Ah[128][72];   // [row][k], 144B stride
    __shared__ __align__(16) __half Bh[64][72];    // [k][col], 144B stride
    int tid = threadIdx.x;
    int row0 = blockIdx.x * 128;
    int lane = tid & 31, wid = tid >> 5;
    int wr = wid >> 1, wc = wid & 1;               // 4x2 warp grid
    int g = lane >> 2, t4 = lane & 3;

    int ra = (lane & 7) + ((lane & 8) ? 8 : 0);
    int ka_off = (lane & 16) ? 8 : 0;
    int rb = (lane & 7) + ((lane & 8) ? 8 : 0);
    int nb_off = (lane & 16) ? 8 : 0;

    float c[2][4][4];
#pragma unroll
    for (int a = 0; a < 2; a++)
#pragma unroll
        for (int b = 0; b < 4; b++)
#pragma unroll
            for (int d = 0; d < 4; d++) c[a][b][d] = 0.f;

    uint32_t ah_base = (uint32_t)__cvta_generic_to_shared(&Ah[0][0]);
    uint32_t bh_base = (uint32_t)__cvta_generic_to_shared(&Bh[0][0]);

    for (int kk0 = 0; kk0 < FIN; kk0 += 64) {
        for (int i = tid; i < 128 * 32; i += 256) {
            int r = i >> 5, c2 = i & 31;
            float2 v = *(const float2*)&x[(size_t)(row0 + r) * FIN + kk0 + 2 * c2];
            *(__half2*)&Ah[r][2 * c2] = __floats2half2_rn(v.x, v.y);
        }
        for (int i = tid; i < 64 * 8; i += 256) {
            int r = i >> 3, q = i & 7;
            *(uint4*)((char*)&Bh[r][0] + q * 16) =
                *(const uint4*)((const char*)(g_w116 + (size_t)(kk0 + r) * HD) + q * 16);
        }
        __syncthreads();
#pragma unroll
        for (int ks = 0; ks < 4; ks++) {
            int k0 = ks * 16;
            uint32_t af[2][4];
#pragma unroll
            for (int mi = 0; mi < 2; mi++) {
                uint32_t off = (uint32_t)((wr * 32 + mi * 16 + ra) * 144 + (k0 + ka_off) * 2);
                ldsm4(af[mi], ah_base + off);
            }
            uint32_t bf[4][2];
#pragma unroll
            for (int p = 0; p < 2; p++) {
                uint32_t off = (uint32_t)((k0 + rb) * 144 + (wc * 32 + p * 16 + nb_off) * 2);
                uint32_t r[4];
                ldsm4t(r, bh_base + off);
                bf[2 * p][0] = r[0]; bf[2 * p][1] = r[1];
                bf[2 * p + 1][0] = r[2]; bf[2 * p + 1][1] = r[3];
            }
#pragma unroll
            for (int mi = 0; mi < 2; mi++)
#pragma unroll
                for (int nj = 0; nj < 4; nj++)
                    mma16816(c[mi][nj], af[mi], bf[nj]);
        }
        __syncthreads();
    }
#pragma unroll
    for (int mi = 0; mi < 2; mi++)
#pragma unroll
        for (int h = 0; h < 2; h++) {
            int rl = wr * 32 + mi * 16 + g + 8 * h;
            size_t base = (size_t)(row0 + rl) * HD;
#pragma unroll
            for (int nj = 0; nj < 4; nj++) {
                int cl = wc * 32 + nj * 8 + 2 * t4;
                *(__half2*)&g_xw16[base + cl] =
                    __floats2half2_rn(c[mi][nj][2 * h], c[mi][nj][2 * h + 1]);
            }
        }
}

// ---------------- aggregation core (warp per node, fp16 gathers) ------------
__device__ __forceinline__ float2 agg_core(const __half* __restrict__ in,
                                           int node, int lane, float dn) {
    const __half2* in2 = (const __half2*)in;
    float2 acc = __half22float2(in2[(size_t)node * 32 + lane]);
    acc.x *= dn; acc.y *= dn;   // self loop (pre dinv[dst] factor)

    int beg = g_row_ptr[node], end = g_row_ptr[node + 1];
    int n = end - beg;
    const int* cp = g_col + beg;
    int nfull = n >> 5;
    for (int b = 0; b < nfull; b++, cp += 32) {
        int s = cp[lane];
        float ds = g_dinv[s];
#pragma unroll 8
        for (int j = 0; j < 32; j++) {
            int   ss = __shfl_sync(0xffffffffu, s, j);
            float dd = __shfl_sync(0xffffffffu, ds, j);
            float2 v = __half22float2(in2[(size_t)ss * 32 + lane]);
            acc.x += v.x * dd;
            acc.y += v.y * dd;
        }
    }
    int rem = n & 31;
    if (rem) {
        int s = 0; float ds = 0.f;
        if (lane < rem) { s = cp[lane]; ds = g_dinv[s]; }
        for (int j = 0; j < rem; j++) {
            int   ss = __shfl_sync(0xffffffffu, s, j);
            float dd = __shfl_sync(0xffffffffu, ds, j);
            float2 v = __half22float2(in2[(size_t)ss * 32 + lane]);
            acc.x += v.x * dd;
            acc.y += v.y * dd;
        }
    }
    return acc;
}

// layer 1: g_h16 = fp16(relu(Â g_xw16 + b1))
__global__ void k_agg1(const float* __restrict__ b1) {
    int gwarp = (blockIdx.x * blockDim.x + threadIdx.x) >> 5;
    int lane = threadIdx.x & 31;
    if (gwarp >= NN) return;
    float dn = g_dinv[gwarp];
    float2 acc = agg_core(g_xw16, gwarp, lane, dn);
    float ox = fmaxf(acc.x * dn + b1[lane * 2], 0.f);
    float oy = fmaxf(acc.y * dn + b1[lane * 2 + 1], 0.f);
    ((__half2*)g_h16)[(size_t)gwarp * 32 + lane] = __floats2half2_rn(ox, oy);
}

// layer 2 aggregation: g_m16 = fp16(Â g_h16)
__global__ void k_agg2() {
    int gwarp = (blockIdx.x * blockDim.x + threadIdx.x) >> 5;
    int lane = threadIdx.x & 31;
    if (gwarp >= NN) return;
    float dn = g_dinv[gwarp];
    float2 acc = agg_core(g_h16, gwarp, lane, dn);
    ((__half2*)g_m16)[(size_t)gwarp * 32 + lane] =
        __floats2half2_rn(acc.x * dn, acc.y * dn);
}

// ---------------- kernel 6: fp16 MMA GEMM, 128x128 tile, 8 warps ----------------
// WRITE=false: compute logits tile, emit per-(colblock,row) (max, sumexp) only.
// WRITE=true : recompute, write  acc + b2[col] - lz[row]  to C (streaming stores).
template <bool WRITE>
__global__ __launch_bounds__(256) void k_mma(const float* __restrict__ b2,
                                             float* __restrict__ C) {
    __shared__ __align__(16) __half Ah[128][72];   // [row][k], 144B stride
    __shared__ __align__(16) __half Bh[64][136];   // [k][col], 272B stride
    __shared__ float sB2[128];
    __shared__ float sLz[128];

    int tid = threadIdx.x;
    int row0 = blockIdx.y * 128, col0 = blockIdx.x * 128;

    for (int i = tid; i < 1024; i += 256) {
        int r = i >> 3, q = i & 7;
        *(uint4*)((char*)&Ah[r][0] + q * 16) =
            *(const uint4*)((const char*)(g_m16 + (size_t)(row0 + r) * HD) + q * 16);
    }
    for (int i = tid; i < 1024; i += 256) {
        int r = i >> 4, q = i & 15;
        *(uint4*)((char*)&Bh[r][0] + q * 16) =
            *(const uint4*)((const char*)(g_w216 + (size_t)r * NN + col0) + q * 16);
    }
    if (tid < 128) {
        sB2[tid] = b2[col0 + tid];
        if (WRITE) sLz[tid] = g_lz[row0 + tid];
    }
    __syncthreads();

    int lane = tid & 31, wid = tid >> 5;
    int wr = wid >> 2, wc = wid & 3;      // warp tile: rows [wr*64,+64), cols [wc*32,+32)
    int g = lane >> 2, t4 = lane & 3;

    float c[4][4][4];
#pragma unroll
    for (int a = 0; a < 4; a++)
#pragma unroll
        for (int b = 0; b < 4; b++)
#pragma unroll
            for (int d = 0; d < 4; d++) c[a][b][d] = 0.f;

    uint32_t ah_base = (uint32_t)__cvta_generic_to_shared(&Ah[0][0]);
    uint32_t bh_base = (uint32_t)__cvta_generic_to_shared(&Bh[0][0]);

    int ra = (lane & 7) + ((lane & 8) ? 8 : 0);
    int ka_off = (lane & 16) ? 8 : 0;
    int rb = (lane & 7) + ((lane & 8) ? 8 : 0);
    int nb_off = (lane & 16) ? 8 : 0;

#pragma unroll
    for (int ks = 0; ks < 4; ks++) {
        int k0 = ks * 16;
        uint32_t ahf[4][4];
#pragma unroll
        for (int mi = 0; mi < 4; mi++) {
            uint32_t off = (uint32_t)((wr * 64 + mi * 16 + ra) * 144 + (k0 + ka_off) * 2);
            ldsm4(ahf[mi], ah_base + off);
        }
        uint32_t bhf[4][2];
#pragma unroll
        for (int p = 0; p < 2; p++) {
            uint32_t off = (uint32_t)((k0 + rb) * 272 + (wc * 32 + p * 16 + nb_off) * 2);
            uint32_t r[4];
            ldsm4t(r, bh_base + off);
            bhf[2 * p][0] = r[0]; bhf[2 * p][1] = r[1];
            bhf[2 * p + 1][0] = r[2]; bhf[2 * p + 1][1] = r[3];
        }
#pragma unroll
        for (int mi = 0; mi < 4; mi++)
#pragma unroll
            for (int nj = 0; nj < 4; nj++)
                mma16816(c[mi][nj], ahf[mi], bhf[nj]);
    }

    if (WRITE) {
#pragma unroll
        for (int mi = 0; mi < 4; mi++)
#pragma unroll
            for (int h = 0; h < 2; h++) {
                int rl = wr * 64 + mi * 16 + g + 8 * h;
                float lz = sLz[rl];
                size_t rowbase = (size_t)(row0 + rl) * NN + col0;
#pragma unroll
                for (int nj = 0; nj < 4; nj++) {
                    int cl = wc * 32 + nj * 8 + 2 * t4;
                    float2 o;
                    o.x = c[mi][nj][2 * h]     + sB2[cl]     - lz;
                    o.y = c[mi][nj][2 * h + 1] + sB2[cl + 1] - lz;
                    __stcs((float2*)&C[rowbase + cl], o);
                }
            }
    } else {
        __syncthreads();                   // done with Ah; overlay stats arrays
        float* sMax = (float*)&Ah[0][0];   // 512 floats
        float* sSum = sMax + 512;
#pragma unroll
        for (int mi = 0; mi < 4; mi++)
#pragma unroll
            for (int h = 0; h < 2; h++) {
                int rl = wr * 64 + mi * 16 + g + 8 * h;
                float v[8];
                float m = -1e30f;
#pragma unroll
                for (int nj = 0; nj < 4; nj++) {
                    int cl = wc * 32 + nj * 8 + 2 * t4;
                    v[2 * nj]     = c[mi][nj][2 * h]     + sB2[cl];
                    v[2 * nj + 1] = c[mi][nj][2 * h + 1] + sB2[cl + 1];
                    m = fmaxf(m, fmaxf(v[2 * nj], v[2 * nj + 1]));
                }
                m = fmaxf(m, __shfl_xor_sync(0xffffffffu, m, 1));
                m = fmaxf(m, __shfl_xor_sync(0xffffffffu, m, 2));
                float s = 0.f;
#pragma unroll
                for (int q = 0; q < 8; q++) s += __expf(v[q] - m);
                s += __shfl_xor_sync(0xffffffffu, s, 1);
                s += __shfl_xor_sync(0xffffffffu, s, 2);
                if (t4 == 0) { sMax[rl * 4 + wc] = m; sSum[rl * 4 + wc] = s; }
            }
        __syncthreads();
        if (tid < 128) {
            float m = -1e30f;
#pragma unroll
            for (int w = 0; w < 4; w++) m = fmaxf(m, sMax[tid * 4 + w]);
            float s = 0.f;
#pragma unroll
            for (int w = 0; w < 4; w++) s += sSum[tid * 4 + w] * __expf(sMax[tid * 4 + w] - m);
            g_pmax[blockIdx.x * NN + row0 + tid] = m;
            g_psum[blockIdx.x * NN + row0 + tid] = s;
        }
    }
}

// ---------------- kernel 7: merge per-colblock stats into lz[row] ----------------
__global__ void k_reduce_lz() {
    int row = blockIdx.x * blockDim.x + threadIdx.x;
    if (row >= NN) return;
    float m = -1e30f;
#pragma unroll 8
    for (int cb = 0; cb < NCB; cb++) m = fmaxf(m, g_pmax[cb * NN + row]);
    float s = 0.f;
#pragma unroll 8
    for (int cb = 0; cb < NCB; cb++)
        s += g_psum[cb * NN + row] * __expf(g_pmax[cb * NN + row] - m);
    g_lz[row] = m + __logf(s);
}

// ---------------- launch ----------------
extern "C" void kernel_launch(void* const* d_in, const int* in_sizes, int n_in,
                              void* d_out, int out_size) {
    const float* x  = (const float*)d_in[0];
    const void*  ei = d_in[1];
    const float* W1 = (const float*)d_in[2];
    const float* b1 = (const float*)d_in[3];
    const float* W2 = (const float*)d_in[4];
    const float* b2 = (const float*)d_in[5];
    float* out = (float*)d_out;

    int E = in_sizes[1] / 2;
    int eblocks4 = (E + 1023) / 1024;

    k_convert_w<<<(NN * HD / 4 + FIN * HD / 4 + 255) / 256, 256>>>(W1, W2);
    k_hist<<<eblocks4, 256>>>(ei, (const int*)ei, E);
    k_scan<<<32, 256>>>();
    k_scatter<<<eblocks4, 256>>>(ei, E);
    k_xw<<<NN / 128, 256>>>(x);
    k_agg1<<<NN / 8, 256>>>(b1);
    k_agg2<<<NN / 8, 256>>>();

    dim3 gg(NCB, NN / 128);
    k_mma<false><<<gg, 256>>>(b2, nullptr);   // stats pass
    k_reduce_lz<<<NN / 256, 256>>>();
    k_mma<true><<<gg, 256>>>(b2, out);        // write pass
}